// round 16
// baseline (speedup 1.0000x reference)
#include <cuda_runtime.h>
#include <cuda_fp16.h>
#include <math.h>
#include <stdint.h>

#define BB 2
#define TT 2048
#define DMODEL 1024
#define NH 16
#define DK 64
#define MROWS (BB * TT)   // 4096

// ---- scratch (static device memory; no allocations allowed) ----
__device__ __half g_qh[(size_t)BB * NH * TT * DK];   // [b][h][t][d] roped+scaled
__device__ __half g_kh[(size_t)BB * NH * TT * DK];   // [b][h][t][d] roped
__device__ __half g_vh[(size_t)BB * NH * DK * TT];   // [b][h][d][t] (transposed)
__device__ __half g_attnh[(size_t)MROWS * DMODEL];   // attention out, fp16
__device__ float  g_cos[TT * 32];
__device__ float  g_sin[TT * 32];

// ---------------------------------------------------------------------------
__device__ __forceinline__ uint32_t pack_h2(float a, float b) {
    __half2 h = __floats2half2_rn(a, b);
    return *reinterpret_cast<uint32_t*>(&h);
}

// m16n8k16 f16, f32 accumulate.
// A: a0=(g,2t:2t+1) a1=(g+8,2t:+1) a2=(g,8+2t:+1) a3=(g+8,8+2t:+1)
// B (col-major view): b0=(k=2t:2t+1, n=g)  b1=(k=8+2t:+1, n=g)
// C: c0=(g,2t) c1=(g,2t+1) c2=(g+8,2t) c3=(g+8,2t+1)
__device__ __forceinline__ void mma_f16(float c[4],
                                        const uint32_t a[4],
                                        uint32_t b0, uint32_t b1) {
    asm volatile(
        "mma.sync.aligned.m16n8k16.row.col.f32.f16.f16.f32 "
        "{%0,%1,%2,%3}, {%4,%5,%6,%7}, {%8,%9}, {%0,%1,%2,%3};"
        : "+f"(c[0]), "+f"(c[1]), "+f"(c[2]), "+f"(c[3])
        : "r"(a[0]), "r"(a[1]), "r"(a[2]), "r"(a[3]), "r"(b0), "r"(b1));
}

// cp.async with .ca (cache ALL levels incl. L1 — co-resident same-head CTAs
// share K/V tiles; .cg was the R7 mistake)
#define CP_ASYNC16_CA(dst, src) \
    asm volatile("cp.async.ca.shared.global [%0], [%1], 16;" :: "r"(dst), "l"(src))
#define CP_COMMIT() asm volatile("cp.async.commit_group;")
#define CP_WAIT0()  asm volatile("cp.async.wait_group 0;")

// ---------------------------------------------------------------------------
// RoPE tables (applied inside the QKV-GEMM epilogue).
// ---------------------------------------------------------------------------
__global__ void rope_table_kernel() {
    int i = blockIdx.x * blockDim.x + threadIdx.x;
    if (i >= TT * 32) return;
    int t = i >> 5, j = i & 31;
    double inv = pow(10000.0, -((double)(2 * j)) / 64.0);
    float angf = (float)t * (float)inv;
    g_cos[i] = (float)cos((double)angf);
    g_sin[i] = (float)sin((double)angf);
}

// ---------------------------------------------------------------------------
// FP16 raw-mma GEMM, warp tile 64Mx64N, CTA 256Mx128N, k-tile 32, occ 1.
// (R15-proven, unchanged.)
// MODE 0: A=x (fp32), W={Wq,Wk,Wv} (fp32); epilogue applies RoPE (+Q scale),
//         scatters q/k -> g_qh/g_kh [b][h][t][d], v -> g_vh transposed.
// MODE 1: A=g_attnh (fp16, internal symbol), W=Wo (fp32), C=out fp32.
// ---------------------------------------------------------------------------
#define LDH 40                        // smem leading dim in halfs
#define ABUF_H (256 * LDH)            // halfs per A buffer
#define BBUF_H (128 * LDH)            // halfs per B buffer
#define STAGE_H (ABUF_H + BBUF_H)
#define GEMM_SMEM (2 * STAGE_H * 2)   // bytes

template <int MODE>
__global__ void __launch_bounds__(256, 1) gemm_mma_kernel(
    const float* __restrict__ A_,
    const float* __restrict__ W0,
    const float* __restrict__ W1,
    const float* __restrict__ W2,
    float* __restrict__ Cout)
{
    extern __shared__ __half gsmh[];

    const int tid = threadIdx.x;
    const int warp = tid >> 5;
    const int lane = tid & 31;
    const int g = lane >> 2;
    const int t = lane & 3;
    const int wm = warp >> 1;            // 0..3 (M, 64 rows each)
    const int wn = warp & 1;             // 0..1 (N, 64 cols each)
    const int mb = blockIdx.x * 256;
    const int nb = blockIdx.y * 128;

    const float* Wp;
    int nloc;
    if (MODE == 0) {
        int w = nb >> 10;
        Wp = (w == 0) ? W0 : ((w == 1) ? W1 : W2);
        nloc = nb & 1023;
    } else {
        Wp = W0;
        nloc = nb;
    }

    const int lrow = tid >> 3;           // base row (step 32)
    const int lkq  = (tid & 7) << 2;     // k offset (4 elements)

    float4 stB[4];
    float4 stA[8];                       // MODE 0 (fp32 A, 256 rows)
    uint2  stAh[8];                      // MODE 1 (fp16 A)

#pragma unroll
    for (int i = 0; i < 8; i++) {
        int row = lrow + 32 * i;
        if (MODE == 0)
            stA[i] = *(const float4*)(A_ + (size_t)(mb + row) * 1024 + lkq);
        else
            stAh[i] = *(const uint2*)(g_attnh + (size_t)(mb + row) * 1024 + lkq);
    }
#pragma unroll
    for (int i = 0; i < 4; i++) {
        int row = lrow + 32 * i;
        stB[i] = *(const float4*)(Wp + (size_t)(nloc + row) * 1024 + lkq);
    }
    {
        __half* As = gsmh;
        __half* Bs = gsmh + ABUF_H;
#pragma unroll
        for (int i = 0; i < 8; i++) {
            int row = lrow + 32 * i;
            if (MODE == 0)
                *(uint2*)&As[row * LDH + lkq] =
                    make_uint2(pack_h2(stA[i].x, stA[i].y), pack_h2(stA[i].z, stA[i].w));
            else
                *(uint2*)&As[row * LDH + lkq] = stAh[i];
        }
#pragma unroll
        for (int i = 0; i < 4; i++) {
            int row = lrow + 32 * i;
            *(uint2*)&Bs[row * LDH + lkq] =
                make_uint2(pack_h2(stB[i].x, stB[i].y), pack_h2(stB[i].z, stB[i].w));
        }
    }
    __syncthreads();

    float c[4][8][4];
#pragma unroll
    for (int i = 0; i < 4; i++)
#pragma unroll
        for (int nt = 0; nt < 8; nt++)
#pragma unroll
            for (int e = 0; e < 4; e++) c[i][nt][e] = 0.f;

    for (int kt = 0; kt < 32; kt++) {
        if (kt + 1 < 32) {
            int kb = (kt + 1) * 32;
#pragma unroll
            for (int i = 0; i < 8; i++) {
                int row = lrow + 32 * i;
                if (MODE == 0)
                    stA[i] = *(const float4*)(A_ + (size_t)(mb + row) * 1024 + kb + lkq);
                else
                    stAh[i] = *(const uint2*)(g_attnh + (size_t)(mb + row) * 1024 + kb + lkq);
            }
#pragma unroll
            for (int i = 0; i < 4; i++) {
                int row = lrow + 32 * i;
                stB[i] = *(const float4*)(Wp + (size_t)(nloc + row) * 1024 + kb + lkq);
            }
        }

        const uint32_t* As_u = (const uint32_t*)(gsmh + (kt & 1) * STAGE_H);
        const uint32_t* Bs_u = As_u + ABUF_H / 2;

#pragma unroll
        for (int k0 = 0; k0 < 2; k0++) {            // k0h = 0, 8 (uint units)
            const int k0h = k0 * 8;
            uint32_t af[4][4];
#pragma unroll
            for (int i = 0; i < 4; i++) {
                int m0 = wm * 64 + i * 16;
                af[i][0] = As_u[(m0 + g)     * (LDH / 2) + k0h + t];
                af[i][1] = As_u[(m0 + g + 8) * (LDH / 2) + k0h + t];
                af[i][2] = As_u[(m0 + g)     * (LDH / 2) + k0h + 4 + t];
                af[i][3] = As_u[(m0 + g + 8) * (LDH / 2) + k0h + 4 + t];
            }
#pragma unroll
            for (int nt = 0; nt < 8; nt++) {
                int n0 = wn * 64 + nt * 8;
                uint32_t b0 = Bs_u[(n0 + g) * (LDH / 2) + k0h + t];
                uint32_t b1 = Bs_u[(n0 + g) * (LDH / 2) + k0h + 4 + t];
                mma_f16(c[0][nt], af[0], b0, b1);
                mma_f16(c[1][nt], af[1], b0, b1);
                mma_f16(c[2][nt], af[2], b0, b1);
                mma_f16(c[3][nt], af[3], b0, b1);
            }
        }

        if (kt + 1 < 32) {
            __half* Asn = gsmh + ((kt + 1) & 1) * STAGE_H;
            __half* Bsn = Asn + ABUF_H;
#pragma unroll
            for (int i = 0; i < 8; i++) {
                int row = lrow + 32 * i;
                if (MODE == 0)
                    *(uint2*)&Asn[row * LDH + lkq] =
                        make_uint2(pack_h2(stA[i].x, stA[i].y), pack_h2(stA[i].z, stA[i].w));
                else
                    *(uint2*)&Asn[row * LDH + lkq] = stAh[i];
            }
#pragma unroll
            for (int i = 0; i < 4; i++) {
                int row = lrow + 32 * i;
                *(uint2*)&Bsn[row * LDH + lkq] =
                    make_uint2(pack_h2(stB[i].x, stB[i].y), pack_h2(stB[i].z, stB[i].w));
            }
            __syncthreads();
        }
    }

    // ---- epilogue (MODE 0: fused RoPE on q/k; V transposed) ----
    const float SCALE = 0.125f * 1.4426950408889634f;
#pragma unroll
    for (int i = 0; i < 4; i++) {
        int m0 = mb + wm * 64 + i * 16;
        int r0 = m0 + g, r1 = m0 + g + 8;
#pragma unroll
        for (int nt = 0; nt < 8; nt++) {
            int ncg = nb + wn * 64 + nt * 8 + 2 * t;
            float c0 = c[i][nt][0], c1 = c[i][nt][1];
            float c2 = c[i][nt][2], c3 = c[i][nt][3];
            if (MODE == 0) {
                int w = ncg >> 10;
                int hn = ncg & 1023;
                int hh = hn >> 6, dd = hn & 63;        // dd even
                int bi0 = r0 >> 11, t0 = r0 & 2047;
                int bi1 = r1 >> 11, t1 = r1 & 2047;
                if (w < 2) {
                    int j = dd >> 1;
                    float cs0 = g_cos[t0 * 32 + j], sn0 = g_sin[t0 * 32 + j];
                    float cs1 = g_cos[t1 * 32 + j], sn1 = g_sin[t1 * 32 + j];
                    float o00 = cs0 * c0 - sn0 * c1;
                    float o01 = sn0 * c0 + cs0 * c1;
                    float o10 = cs1 * c2 - sn1 * c3;
                    float o11 = sn1 * c2 + cs1 * c3;
                    if (w == 0) { o00 *= SCALE; o01 *= SCALE; o10 *= SCALE; o11 *= SCALE; }
                    __half* dst = (w == 0) ? g_qh : g_kh;
                    *(__half2*)&dst[((size_t)(bi0 * NH + hh) * TT + t0) * DK + dd] =
                        __floats2half2_rn(o00, o01);
                    *(__half2*)&dst[((size_t)(bi1 * NH + hh) * TT + t1) * DK + dd] =
                        __floats2half2_rn(o10, o11);
                } else {
                    size_t b0i = ((size_t)(bi0 * NH + hh) * DK + dd) * TT + t0;
                    g_vh[b0i]      = __float2half_rn(c0);
                    g_vh[b0i + TT] = __float2half_rn(c1);
                    size_t b1i = ((size_t)(bi1 * NH + hh) * DK + dd) * TT + t1;
                    g_vh[b1i]      = __float2half_rn(c2);
                    g_vh[b1i + TT] = __float2half_rn(c3);
                }
            } else {
                *(float2*)&Cout[(size_t)r0 * DMODEL + ncg] = make_float2(c0, c1);
                *(float2*)&Cout[(size_t)r1 * DMODEL + ncg] = make_float2(c2, c3);
            }
        }
    }
}

// ---------------------------------------------------------------------------
// Flash attention, fp16 m16n8k16, cp.async.CA double-buffered K/V
// (R7-proven pipeline structure, .ca instead of the mistaken .cg):
// 1 __syncthreads per k-tile, async loads off the critical path, L1 reuse
// across co-resident same-head CTAs preserved. qt descending.
// smem: 2x { Ks[64][72], Vt[64][72] } halfs.
// ---------------------------------------------------------------------------
#define LDKH 72
#define KVBUF (64 * LDKH)                   // halfs per K (or V) buffer
#define FLASH_SMEM (4 * KVBUF * 2)          // bytes

__global__ void __launch_bounds__(256, 2) flash_mma_kernel() {
    extern __shared__ __half fsh[];
    __half* Kb[2] = { fsh,             fsh + 2 * KVBUF };
    __half* Vb[2] = { fsh + KVBUF,     fsh + 3 * KVBUF };

    const int qt = (gridDim.x - 1) - blockIdx.x;   // long CTAs first
    const int h  = blockIdx.y;
    const int bz = blockIdx.z;
    const int tid = threadIdx.x;
    const int lane = tid & 31;
    const int w = tid >> 5;
    const int g = lane >> 2;
    const int t = lane & 3;

    const size_t head_off = (size_t)(bz * NH + h) * TT * DK;
    const int rbase = qt * 128 + w * 16;

    const __half* kbase = g_kh + head_off;
    const __half* vbase = g_vh + (size_t)(bz * NH + h) * DK * TT;

    // per-thread fill slots: 2 x 16B chunks for K, same for V
    const int r0f = tid >> 3;                     // rows (step 32)
    const int cqf = (tid & 7) * 8;                // col offset (halfs)

    // ---- Q fragments (fp16, roped + pre-scaled by GEMM epilogue) ----
    uint32_t qf[4][4];
    {
        const __half* qp = g_qh + head_off + (size_t)rbase * DK;
#pragma unroll
        for (int kc = 0; kc < 4; kc++) {
            qf[kc][0] = *(const uint32_t*)&qp[(size_t)g * DK + 16 * kc + 2 * t];
            qf[kc][1] = *(const uint32_t*)&qp[(size_t)(g + 8) * DK + 16 * kc + 2 * t];
            qf[kc][2] = *(const uint32_t*)&qp[(size_t)g * DK + 16 * kc + 8 + 2 * t];
            qf[kc][3] = *(const uint32_t*)&qp[(size_t)(g + 8) * DK + 16 * kc + 8 + 2 * t];
        }
    }

    float oa[8][4];
#pragma unroll
    for (int i = 0; i < 8; i++)
#pragma unroll
        for (int j = 0; j < 4; j++) oa[i][j] = 0.f;
    float m0 = -1e30f, m1 = -1e30f, l0 = 0.f, l1 = 0.f;

    const int ktiles = 2 * qt + 2;

    // ---- prologue: async-fill tile 0 into buffer 0 ----
    {
#pragma unroll
        for (int i = 0; i < 2; i++) {
            int r = r0f + 32 * i;
            uint32_t dk_ = (uint32_t)__cvta_generic_to_shared(&Kb[0][r * LDKH + cqf]);
            uint32_t dv_ = (uint32_t)__cvta_generic_to_shared(&Vb[0][r * LDKH + cqf]);
            CP_ASYNC16_CA(dk_, kbase + (size_t)r * DK + cqf);
            CP_ASYNC16_CA(dv_, vbase + (size_t)r * TT + cqf);
        }
        CP_COMMIT();
    }

    for (int j = 0; j < ktiles; j++) {
        CP_WAIT0();
        __syncthreads();   // tile j resident; all warps finished tile j-1
                           // (so buffer (j+1)&1 is free for the prefetch below)

        if (j + 1 < ktiles) {
            const __half* kp = kbase + (size_t)(j + 1) * 64 * DK;
            const __half* vp = vbase + 64 * (j + 1);
            __half* Kd = Kb[(j + 1) & 1];
            __half* Vd = Vb[(j + 1) & 1];
#pragma unroll
            for (int i = 0; i < 2; i++) {
                int r = r0f + 32 * i;
                uint32_t dk_ = (uint32_t)__cvta_generic_to_shared(&Kd[r * LDKH + cqf]);
                uint32_t dv_ = (uint32_t)__cvta_generic_to_shared(&Vd[r * LDKH + cqf]);
                CP_ASYNC16_CA(dk_, kp + (size_t)r * DK + cqf);
                CP_ASYNC16_CA(dv_, vp + (size_t)r * TT + cqf);
            }
            CP_COMMIT();
        }

        if (64 * j > rbase + 15) continue;   // warp fully above diagonal

        const uint32_t* Ks_u = (const uint32_t*)Kb[j & 1];
        const uint32_t* Vt_u = (const uint32_t*)Vb[j & 1];

        // ---- S = Q K^T ----
        float sa[8][4];
#pragma unroll
        for (int nt = 0; nt < 8; nt++) {
            sa[nt][0] = sa[nt][1] = sa[nt][2] = sa[nt][3] = 0.f;
#pragma unroll
            for (int kc = 0; kc < 4; kc++) {
                uint32_t b0 = Ks_u[(8 * nt + g) * (LDKH / 2) + 8 * kc + t];
                uint32_t b1 = Ks_u[(8 * nt + g) * (LDKH / 2) + 8 * kc + 4 + t];
                mma_f16(sa[nt], qf[kc], b0, b1);
            }
        }

        // ---- causal mask (diagonal region only) ----
        if (64 * j + 63 > rbase) {
            const int r0 = rbase + g, r1 = rbase + g + 8;
#pragma unroll
            for (int nt = 0; nt < 8; nt++) {
                int c0 = 64 * j + 8 * nt + 2 * t;
                if (c0 > r0)     sa[nt][0] = -1e30f;
                if (c0 + 1 > r0) sa[nt][1] = -1e30f;
                if (c0 > r1)     sa[nt][2] = -1e30f;
                if (c0 + 1 > r1) sa[nt][3] = -1e30f;
            }
        }

        // ---- online softmax (registers + quad shuffles) ----
        float mx0 = -1e30f, mx1 = -1e30f;
#pragma unroll
        for (int nt = 0; nt < 8; nt++) {
            mx0 = fmaxf(mx0, fmaxf(sa[nt][0], sa[nt][1]));
            mx1 = fmaxf(mx1, fmaxf(sa[nt][2], sa[nt][3]));
        }
        mx0 = fmaxf(mx0, __shfl_xor_sync(0xffffffffu, mx0, 1));
        mx0 = fmaxf(mx0, __shfl_xor_sync(0xffffffffu, mx0, 2));
        mx1 = fmaxf(mx1, __shfl_xor_sync(0xffffffffu, mx1, 1));
        mx1 = fmaxf(mx1, __shfl_xor_sync(0xffffffffu, mx1, 2));
        float mn0 = fmaxf(m0, mx0), mn1 = fmaxf(m1, mx1);
        float al0 = exp2f(m0 - mn0), al1 = exp2f(m1 - mn1);
        m0 = mn0; m1 = mn1;

        float sum0 = 0.f, sum1 = 0.f;
#pragma unroll
        for (int nt = 0; nt < 8; nt++) {
            float p0 = exp2f(sa[nt][0] - mn0);
            float p1 = exp2f(sa[nt][1] - mn0);
            float p2 = exp2f(sa[nt][2] - mn1);
            float p3 = exp2f(sa[nt][3] - mn1);
            sum0 += p0 + p1;
            sum1 += p2 + p3;
            sa[nt][0] = p0; sa[nt][1] = p1; sa[nt][2] = p2; sa[nt][3] = p3;
        }
        sum0 += __shfl_xor_sync(0xffffffffu, sum0, 1);
        sum0 += __shfl_xor_sync(0xffffffffu, sum0, 2);
        sum1 += __shfl_xor_sync(0xffffffffu, sum1, 1);
        sum1 += __shfl_xor_sync(0xffffffffu, sum1, 2);
        l0 = l0 * al0 + sum0;
        l1 = l1 * al1 + sum1;

#pragma unroll
        for (int dt = 0; dt < 8; dt++) {
            oa[dt][0] *= al0; oa[dt][1] *= al0;
            oa[dt][2] *= al1; oa[dt][3] *= al1;
        }

        // ---- pack P to fp16 A-fragments (registers only) ----
        uint32_t pf[4][4];
#pragma unroll
        for (int kc = 0; kc < 4; kc++) {
            pf[kc][0] = pack_h2(sa[2 * kc][0],     sa[2 * kc][1]);
            pf[kc][1] = pack_h2(sa[2 * kc][2],     sa[2 * kc][3]);
            pf[kc][2] = pack_h2(sa[2 * kc + 1][0], sa[2 * kc + 1][1]);
            pf[kc][3] = pack_h2(sa[2 * kc + 1][2], sa[2 * kc + 1][3]);
        }

        // ---- O += P V ----
#pragma unroll
        for (int kc = 0; kc < 4; kc++) {
#pragma unroll
            for (int dt = 0; dt < 8; dt++) {
                uint32_t b0 = Vt_u[(8 * dt + g) * (LDKH / 2) + 8 * kc + t];
                uint32_t b1 = Vt_u[(8 * dt + g) * (LDKH / 2) + 8 * kc + 4 + t];
                mma_f16(oa[dt], pf[kc], b0, b1);
            }
        }
    }

    // ---- normalize & write fp16 [b*t][e] ----
    {
        float inv0 = 1.f / l0, inv1 = 1.f / l1;
        __half* op0 = g_attnh + (size_t)(bz * TT + rbase + g) * DMODEL + h * DK;
        __half* op1 = g_attnh + (size_t)(bz * TT + rbase + g + 8) * DMODEL + h * DK;
#pragma unroll
        for (int dt = 0; dt < 8; dt++) {
            *(uint32_t*)&op0[8 * dt + 2 * t] = pack_h2(oa[dt][0] * inv0, oa[dt][1] * inv0);
            *(uint32_t*)&op1[8 * dt + 2 * t] = pack_h2(oa[dt][2] * inv1, oa[dt][3] * inv1);
        }
    }
}

// ---------------------------------------------------------------------------
extern "C" void kernel_launch(void* const* d_in, const int* in_sizes, int n_in,
                              void* d_out, int out_size) {
    (void)in_sizes; (void)n_in; (void)out_size;
    const float* x  = (const float*)d_in[0];
    const float* Wq = (const float*)d_in[2];
    const float* Wk = (const float*)d_in[3];
    const float* Wv = (const float*)d_in[4];
    const float* Wo = (const float*)d_in[5];
    float* out = (float*)d_out;

    cudaFuncSetAttribute(flash_mma_kernel,
                         cudaFuncAttributeMaxDynamicSharedMemorySize, FLASH_SMEM);
    cudaFuncSetAttribute(gemm_mma_kernel<0>,
                         cudaFuncAttributeMaxDynamicSharedMemorySize, GEMM_SMEM);
    cudaFuncSetAttribute(gemm_mma_kernel<1>,
                         cudaFuncAttributeMaxDynamicSharedMemorySize, GEMM_SMEM);

    rope_table_kernel<<<(TT * 32 + 255) / 256, 256>>>();

    gemm_mma_kernel<0><<<dim3(MROWS / 256, 3072 / 128), 256, GEMM_SMEM>>>(
        x, Wq, Wk, Wv, nullptr);

    flash_mma_kernel<<<dim3(TT / 128, NH, BB), 256, FLASH_SMEM>>>();

    gemm_mma_kernel<1><<<dim3(MROWS / 256, DMODEL / 128), 256, GEMM_SMEM>>>(
        nullptr, Wo, nullptr, nullptr, out);
}

// round 17
// speedup vs baseline: 1.0691x; 1.0691x over previous
#include <cuda_runtime.h>
#include <cuda_fp16.h>
#include <math.h>
#include <stdint.h>

#define BB 2
#define TT 2048
#define DMODEL 1024
#define NH 16
#define DK 64
#define MROWS (BB * TT)   // 4096

// ---- scratch (static device memory; no allocations allowed) ----
__device__ __half g_qh[(size_t)BB * NH * TT * DK];   // [b][h][t][d] roped+scaled
__device__ __half g_kh[(size_t)BB * NH * TT * DK];   // [b][h][t][d] roped
__device__ __half g_vh[(size_t)BB * NH * DK * TT];   // [b][h][d][t] (transposed)
__device__ __half g_attnh[(size_t)MROWS * DMODEL];   // attention out, fp16
__device__ float  g_cos[TT * 32];
__device__ float  g_sin[TT * 32];

// ---------------------------------------------------------------------------
__device__ __forceinline__ uint32_t pack_h2(float a, float b) {
    __half2 h = __floats2half2_rn(a, b);
    return *reinterpret_cast<uint32_t*>(&h);
}

// m16n8k16 f16, f32 accumulate.
// A: a0=(g,2t:2t+1) a1=(g+8,2t:+1) a2=(g,8+2t:+1) a3=(g+8,8+2t:+1)
// B (col-major view): b0=(k=2t:2t+1, n=g)  b1=(k=8+2t:+1, n=g)
// C: c0=(g,2t) c1=(g,2t+1) c2=(g+8,2t) c3=(g+8,2t+1)
__device__ __forceinline__ void mma_f16(float c[4],
                                        const uint32_t a[4],
                                        uint32_t b0, uint32_t b1) {
    asm volatile(
        "mma.sync.aligned.m16n8k16.row.col.f32.f16.f16.f32 "
        "{%0,%1,%2,%3}, {%4,%5,%6,%7}, {%8,%9}, {%0,%1,%2,%3};"
        : "+f"(c[0]), "+f"(c[1]), "+f"(c[2]), "+f"(c[3])
        : "r"(a[0]), "r"(a[1]), "r"(a[2]), "r"(a[3]), "r"(b0), "r"(b1));
}

// ldmatrix x4: r0..r3 = four 8x8 fp16 matrices; lane row-addressing gives
// r0/r1 = b0/b1 of pair element 0, r2/r3 = b0/b1 of pair element 1.
// (Mapping hardware-verified in the R12 GEMM run.)
__device__ __forceinline__ void ldsm_x4(uint32_t r[4], uint32_t addr) {
    asm volatile("ldmatrix.sync.aligned.m8n8.x4.shared.b16 {%0,%1,%2,%3}, [%4];"
        : "=r"(r[0]), "=r"(r[1]), "=r"(r[2]), "=r"(r[3]) : "r"(addr));
}

// ---------------------------------------------------------------------------
// RoPE tables (applied inside the QKV-GEMM epilogue).
// ---------------------------------------------------------------------------
__global__ void rope_table_kernel() {
    int i = blockIdx.x * blockDim.x + threadIdx.x;
    if (i >= TT * 32) return;
    int t = i >> 5, j = i & 31;
    double inv = pow(10000.0, -((double)(2 * j)) / 64.0);
    float angf = (float)t * (float)inv;
    g_cos[i] = (float)cos((double)angf);
    g_sin[i] = (float)sin((double)angf);
}

// ---------------------------------------------------------------------------
// FP16 raw-mma GEMM, warp tile 64Mx64N, CTA 256Mx128N, k-tile 32, occ 1.
// (R15-proven, unchanged.)
// MODE 0: A=x (fp32), W={Wq,Wk,Wv} (fp32); epilogue applies RoPE (+Q scale),
//         scatters q/k -> g_qh/g_kh [b][h][t][d], v -> g_vh transposed.
// MODE 1: A=g_attnh (fp16, internal symbol), W=Wo (fp32), C=out fp32.
// ---------------------------------------------------------------------------
#define LDH 40                        // smem leading dim in halfs
#define ABUF_H (256 * LDH)            // halfs per A buffer
#define BBUF_H (128 * LDH)            // halfs per B buffer
#define STAGE_H (ABUF_H + BBUF_H)
#define GEMM_SMEM (2 * STAGE_H * 2)   // bytes

template <int MODE>
__global__ void __launch_bounds__(256, 1) gemm_mma_kernel(
    const float* __restrict__ A_,
    const float* __restrict__ W0,
    const float* __restrict__ W1,
    const float* __restrict__ W2,
    float* __restrict__ Cout)
{
    extern __shared__ __half gsmh[];

    const int tid = threadIdx.x;
    const int warp = tid >> 5;
    const int lane = tid & 31;
    const int g = lane >> 2;
    const int t = lane & 3;
    const int wm = warp >> 1;            // 0..3 (M, 64 rows each)
    const int wn = warp & 1;             // 0..1 (N, 64 cols each)
    const int mb = blockIdx.x * 256;
    const int nb = blockIdx.y * 128;

    const float* Wp;
    int nloc;
    if (MODE == 0) {
        int w = nb >> 10;
        Wp = (w == 0) ? W0 : ((w == 1) ? W1 : W2);
        nloc = nb & 1023;
    } else {
        Wp = W0;
        nloc = nb;
    }

    const int lrow = tid >> 3;           // base row (step 32)
    const int lkq  = (tid & 7) << 2;     // k offset (4 elements)

    float4 stB[4];
    float4 stA[8];                       // MODE 0 (fp32 A, 256 rows)
    uint2  stAh[8];                      // MODE 1 (fp16 A)

#pragma unroll
    for (int i = 0; i < 8; i++) {
        int row = lrow + 32 * i;
        if (MODE == 0)
            stA[i] = *(const float4*)(A_ + (size_t)(mb + row) * 1024 + lkq);
        else
            stAh[i] = *(const uint2*)(g_attnh + (size_t)(mb + row) * 1024 + lkq);
    }
#pragma unroll
    for (int i = 0; i < 4; i++) {
        int row = lrow + 32 * i;
        stB[i] = *(const float4*)(Wp + (size_t)(nloc + row) * 1024 + lkq);
    }
    {
        __half* As = gsmh;
        __half* Bs = gsmh + ABUF_H;
#pragma unroll
        for (int i = 0; i < 8; i++) {
            int row = lrow + 32 * i;
            if (MODE == 0)
                *(uint2*)&As[row * LDH + lkq] =
                    make_uint2(pack_h2(stA[i].x, stA[i].y), pack_h2(stA[i].z, stA[i].w));
            else
                *(uint2*)&As[row * LDH + lkq] = stAh[i];
        }
#pragma unroll
        for (int i = 0; i < 4; i++) {
            int row = lrow + 32 * i;
            *(uint2*)&Bs[row * LDH + lkq] =
                make_uint2(pack_h2(stB[i].x, stB[i].y), pack_h2(stB[i].z, stB[i].w));
        }
    }
    __syncthreads();

    float c[4][8][4];
#pragma unroll
    for (int i = 0; i < 4; i++)
#pragma unroll
        for (int nt = 0; nt < 8; nt++)
#pragma unroll
            for (int e = 0; e < 4; e++) c[i][nt][e] = 0.f;

    for (int kt = 0; kt < 32; kt++) {
        if (kt + 1 < 32) {
            int kb = (kt + 1) * 32;
#pragma unroll
            for (int i = 0; i < 8; i++) {
                int row = lrow + 32 * i;
                if (MODE == 0)
                    stA[i] = *(const float4*)(A_ + (size_t)(mb + row) * 1024 + kb + lkq);
                else
                    stAh[i] = *(const uint2*)(g_attnh + (size_t)(mb + row) * 1024 + kb + lkq);
            }
#pragma unroll
            for (int i = 0; i < 4; i++) {
                int row = lrow + 32 * i;
                stB[i] = *(const float4*)(Wp + (size_t)(nloc + row) * 1024 + kb + lkq);
            }
        }

        const uint32_t* As_u = (const uint32_t*)(gsmh + (kt & 1) * STAGE_H);
        const uint32_t* Bs_u = As_u + ABUF_H / 2;

#pragma unroll
        for (int k0 = 0; k0 < 2; k0++) {            // k0h = 0, 8 (uint units)
            const int k0h = k0 * 8;
            uint32_t af[4][4];
#pragma unroll
            for (int i = 0; i < 4; i++) {
                int m0 = wm * 64 + i * 16;
                af[i][0] = As_u[(m0 + g)     * (LDH / 2) + k0h + t];
                af[i][1] = As_u[(m0 + g + 8) * (LDH / 2) + k0h + t];
                af[i][2] = As_u[(m0 + g)     * (LDH / 2) + k0h + 4 + t];
                af[i][3] = As_u[(m0 + g + 8) * (LDH / 2) + k0h + 4 + t];
            }
#pragma unroll
            for (int nt = 0; nt < 8; nt++) {
                int n0 = wn * 64 + nt * 8;
                uint32_t b0 = Bs_u[(n0 + g) * (LDH / 2) + k0h + t];
                uint32_t b1 = Bs_u[(n0 + g) * (LDH / 2) + k0h + 4 + t];
                mma_f16(c[0][nt], af[0], b0, b1);
                mma_f16(c[1][nt], af[1], b0, b1);
                mma_f16(c[2][nt], af[2], b0, b1);
                mma_f16(c[3][nt], af[3], b0, b1);
            }
        }

        if (kt + 1 < 32) {
            __half* Asn = gsmh + ((kt + 1) & 1) * STAGE_H;
            __half* Bsn = Asn + ABUF_H;
#pragma unroll
            for (int i = 0; i < 8; i++) {
                int row = lrow + 32 * i;
                if (MODE == 0)
                    *(uint2*)&Asn[row * LDH + lkq] =
                        make_uint2(pack_h2(stA[i].x, stA[i].y), pack_h2(stA[i].z, stA[i].w));
                else
                    *(uint2*)&Asn[row * LDH + lkq] = stAh[i];
            }
#pragma unroll
            for (int i = 0; i < 4; i++) {
                int row = lrow + 32 * i;
                *(uint2*)&Bsn[row * LDH + lkq] =
                    make_uint2(pack_h2(stB[i].x, stB[i].y), pack_h2(stB[i].z, stB[i].w));
            }
            __syncthreads();
        }
    }

    // ---- epilogue (MODE 0: fused RoPE on q/k; V transposed) ----
    const float SCALE = 0.125f * 1.4426950408889634f;
#pragma unroll
    for (int i = 0; i < 4; i++) {
        int m0 = mb + wm * 64 + i * 16;
        int r0 = m0 + g, r1 = m0 + g + 8;
#pragma unroll
        for (int nt = 0; nt < 8; nt++) {
            int ncg = nb + wn * 64 + nt * 8 + 2 * t;
            float c0 = c[i][nt][0], c1 = c[i][nt][1];
            float c2 = c[i][nt][2], c3 = c[i][nt][3];
            if (MODE == 0) {
                int w = ncg >> 10;
                int hn = ncg & 1023;
                int hh = hn >> 6, dd = hn & 63;        // dd even
                int bi0 = r0 >> 11, t0 = r0 & 2047;
                int bi1 = r1 >> 11, t1 = r1 & 2047;
                if (w < 2) {
                    int j = dd >> 1;
                    float cs0 = g_cos[t0 * 32 + j], sn0 = g_sin[t0 * 32 + j];
                    float cs1 = g_cos[t1 * 32 + j], sn1 = g_sin[t1 * 32 + j];
                    float o00 = cs0 * c0 - sn0 * c1;
                    float o01 = sn0 * c0 + cs0 * c1;
                    float o10 = cs1 * c2 - sn1 * c3;
                    float o11 = sn1 * c2 + cs1 * c3;
                    if (w == 0) { o00 *= SCALE; o01 *= SCALE; o10 *= SCALE; o11 *= SCALE; }
                    __half* dst = (w == 0) ? g_qh : g_kh;
                    *(__half2*)&dst[((size_t)(bi0 * NH + hh) * TT + t0) * DK + dd] =
                        __floats2half2_rn(o00, o01);
                    *(__half2*)&dst[((size_t)(bi1 * NH + hh) * TT + t1) * DK + dd] =
                        __floats2half2_rn(o10, o11);
                } else {
                    size_t b0i = ((size_t)(bi0 * NH + hh) * DK + dd) * TT + t0;
                    g_vh[b0i]      = __float2half_rn(c0);
                    g_vh[b0i + TT] = __float2half_rn(c1);
                    size_t b1i = ((size_t)(bi1 * NH + hh) * DK + dd) * TT + t1;
                    g_vh[b1i]      = __float2half_rn(c2);
                    g_vh[b1i + TT] = __float2half_rn(c3);
                }
            } else {
                *(float2*)&Cout[(size_t)r0 * DMODEL + ncg] = make_float2(c0, c1);
                *(float2*)&Cout[(size_t)r1 * DMODEL + ncg] = make_float2(c2, c3);
            }
        }
    }
}

// ---------------------------------------------------------------------------
// Flash attention, fp16 m16n8k16.  R15 structure (sync LDG->STS, L1-cached,
// 2 barriers/iter, qt descending) + ldmatrix.x4 fragment loads for S and PV
// (64 scalar LDS -> 16 LDSM per phase per warp).
// smem: Ks[64][72] halfs ([c][d]), Vt[64][72] halfs ([d][c]).
// ---------------------------------------------------------------------------
#define LDKH 72
#define FLASH_SMEM (2 * 64 * LDKH * 2)

__global__ void __launch_bounds__(256, 2) flash_mma_kernel() {
    extern __shared__ __half fsh[];
    __half* Ks = fsh;                   // [c][d]
    __half* Vt = fsh + 64 * LDKH;       // [d][c]

    const int qt = (gridDim.x - 1) - blockIdx.x;   // long CTAs first
    const int h  = blockIdx.y;
    const int bz = blockIdx.z;
    const int tid = threadIdx.x;
    const int lane = tid & 31;
    const int w = tid >> 5;
    const int g = lane >> 2;
    const int t = lane & 3;

    const size_t head_off = (size_t)(bz * NH + h) * TT * DK;
    const int rbase = qt * 128 + w * 16;

    const __half* kbase = g_kh + head_off;
    const __half* vbase = g_vh + (size_t)(bz * NH + h) * DK * TT;

    // ldmatrix base addresses (byte offsets shared by K and V tiles)
    const uint32_t ks_u32 = (uint32_t)__cvta_generic_to_shared(Ks);
    const uint32_t vt_u32 = (uint32_t)__cvta_generic_to_shared(Vt);
    const int lrow_m = (lane & 7) + ((lane >> 4) & 1) * 8;   // row within 16-pair
    const int lcol_m = ((lane >> 3) & 1) * 8;                // col (halfs)
    uint32_t pair_off[4];
#pragma unroll
    for (int p = 0; p < 4; p++)
        pair_off[p] = ((p * 16 + lrow_m) * LDKH + lcol_m) * 2;   // bytes

    // ---- Q fragments (fp16, roped + pre-scaled by GEMM epilogue) ----
    uint32_t qf[4][4];
    {
        const __half* qp = g_qh + head_off + (size_t)rbase * DK;
#pragma unroll
        for (int kc = 0; kc < 4; kc++) {
            qf[kc][0] = *(const uint32_t*)&qp[(size_t)g * DK + 16 * kc + 2 * t];
            qf[kc][1] = *(const uint32_t*)&qp[(size_t)(g + 8) * DK + 16 * kc + 2 * t];
            qf[kc][2] = *(const uint32_t*)&qp[(size_t)g * DK + 16 * kc + 8 + 2 * t];
            qf[kc][3] = *(const uint32_t*)&qp[(size_t)(g + 8) * DK + 16 * kc + 8 + 2 * t];
        }
    }

    float oa[8][4];
#pragma unroll
    for (int i = 0; i < 8; i++)
#pragma unroll
        for (int j = 0; j < 4; j++) oa[i][j] = 0.f;
    float m0 = -1e30f, m1 = -1e30f, l0 = 0.f, l1 = 0.f;

    const int ktiles = 2 * qt + 2;
    for (int j = 0; j < ktiles; j++) {
        __syncthreads();
        {
            const __half* kp = kbase + (size_t)j * 64 * DK;
            const __half* vp = vbase + 64 * j;
#pragma unroll
            for (int i = 0; i < 2; i++) {
                int f8 = tid + 256 * i;          // 8-half (16B) chunk id
                int r = f8 >> 3, cq = (f8 & 7) * 8;
                *(uint4*)&Ks[r * LDKH + cq] = *(const uint4*)(kp + r * DK + cq);
                *(uint4*)&Vt[r * LDKH + cq] = *(const uint4*)(vp + (size_t)r * TT + cq);
            }
        }
        __syncthreads();

        if (64 * j > rbase + 15) continue;

        // ---- S = Q K^T (ldmatrix B-fragments, nt pairs) ----
        float sa[8][4];
#pragma unroll
        for (int nt = 0; nt < 8; nt++)
            sa[nt][0] = sa[nt][1] = sa[nt][2] = sa[nt][3] = 0.f;
#pragma unroll
        for (int p = 0; p < 4; p++) {            // nt = 2p, 2p+1
            uint32_t kaddr = ks_u32 + pair_off[p];
#pragma unroll
            for (int kc = 0; kc < 4; kc++) {
                uint32_t bf[4];
                ldsm_x4(bf, kaddr + kc * 32);
                mma_f16(sa[2 * p],     qf[kc], bf[0], bf[1]);
                mma_f16(sa[2 * p + 1], qf[kc], bf[2], bf[3]);
            }
        }

        // ---- causal mask (diagonal region only) ----
        if (64 * j + 63 > rbase) {
            const int r0 = rbase + g, r1 = rbase + g + 8;
#pragma unroll
            for (int nt = 0; nt < 8; nt++) {
                int c0 = 64 * j + 8 * nt + 2 * t;
                if (c0 > r0)     sa[nt][0] = -1e30f;
                if (c0 + 1 > r0) sa[nt][1] = -1e30f;
                if (c0 > r1)     sa[nt][2] = -1e30f;
                if (c0 + 1 > r1) sa[nt][3] = -1e30f;
            }
        }

        // ---- online softmax (registers + quad shuffles) ----
        float mx0 = -1e30f, mx1 = -1e30f;
#pragma unroll
        for (int nt = 0; nt < 8; nt++) {
            mx0 = fmaxf(mx0, fmaxf(sa[nt][0], sa[nt][1]));
            mx1 = fmaxf(mx1, fmaxf(sa[nt][2], sa[nt][3]));
        }
        mx0 = fmaxf(mx0, __shfl_xor_sync(0xffffffffu, mx0, 1));
        mx0 = fmaxf(mx0, __shfl_xor_sync(0xffffffffu, mx0, 2));
        mx1 = fmaxf(mx1, __shfl_xor_sync(0xffffffffu, mx1, 1));
        mx1 = fmaxf(mx1, __shfl_xor_sync(0xffffffffu, mx1, 2));
        float mn0 = fmaxf(m0, mx0), mn1 = fmaxf(m1, mx1);
        float al0 = exp2f(m0 - mn0), al1 = exp2f(m1 - mn1);
        m0 = mn0; m1 = mn1;

        float sum0 = 0.f, sum1 = 0.f;
#pragma unroll
        for (int nt = 0; nt < 8; nt++) {
            float p0 = exp2f(sa[nt][0] - mn0);
            float p1 = exp2f(sa[nt][1] - mn0);
            float p2 = exp2f(sa[nt][2] - mn1);
            float p3 = exp2f(sa[nt][3] - mn1);
            sum0 += p0 + p1;
            sum1 += p2 + p3;
            sa[nt][0] = p0; sa[nt][1] = p1; sa[nt][2] = p2; sa[nt][3] = p3;
        }
        sum0 += __shfl_xor_sync(0xffffffffu, sum0, 1);
        sum0 += __shfl_xor_sync(0xffffffffu, sum0, 2);
        sum1 += __shfl_xor_sync(0xffffffffu, sum1, 1);
        sum1 += __shfl_xor_sync(0xffffffffu, sum1, 2);
        l0 = l0 * al0 + sum0;
        l1 = l1 * al1 + sum1;

#pragma unroll
        for (int dt = 0; dt < 8; dt++) {
            oa[dt][0] *= al0; oa[dt][1] *= al0;
            oa[dt][2] *= al1; oa[dt][3] *= al1;
        }

        // ---- pack P to fp16 A-fragments (registers only) ----
        uint32_t pf[4][4];
#pragma unroll
        for (int kc = 0; kc < 4; kc++) {
            pf[kc][0] = pack_h2(sa[2 * kc][0],     sa[2 * kc][1]);
            pf[kc][1] = pack_h2(sa[2 * kc][2],     sa[2 * kc][3]);
            pf[kc][2] = pack_h2(sa[2 * kc + 1][0], sa[2 * kc + 1][1]);
            pf[kc][3] = pack_h2(sa[2 * kc + 1][2], sa[2 * kc + 1][3]);
        }

        // ---- O += P V (ldmatrix B-fragments, dt pairs) ----
#pragma unroll
        for (int p = 0; p < 4; p++) {            // dt = 2p, 2p+1
            uint32_t vaddr = vt_u32 + pair_off[p];
#pragma unroll
            for (int kc = 0; kc < 4; kc++) {
                uint32_t bf[4];
                ldsm_x4(bf, vaddr + kc * 32);
                mma_f16(oa[2 * p],     pf[kc], bf[0], bf[1]);
                mma_f16(oa[2 * p + 1], pf[kc], bf[2], bf[3]);
            }
        }
    }

    // ---- normalize & write fp16 [b*t][e] ----
    {
        float inv0 = 1.f / l0, inv1 = 1.f / l1;
        __half* op0 = g_attnh + (size_t)(bz * TT + rbase + g) * DMODEL + h * DK;
        __half* op1 = g_attnh + (size_t)(bz * TT + rbase + g + 8) * DMODEL + h * DK;
#pragma unroll
        for (int dt = 0; dt < 8; dt++) {
            *(uint32_t*)&op0[8 * dt + 2 * t] = pack_h2(oa[dt][0] * inv0, oa[dt][1] * inv0);
            *(uint32_t*)&op1[8 * dt + 2 * t] = pack_h2(oa[dt][2] * inv1, oa[dt][3] * inv1);
        }
    }
}

// ---------------------------------------------------------------------------
extern "C" void kernel_launch(void* const* d_in, const int* in_sizes, int n_in,
                              void* d_out, int out_size) {
    (void)in_sizes; (void)n_in; (void)out_size;
    const float* x  = (const float*)d_in[0];
    const float* Wq = (const float*)d_in[2];
    const float* Wk = (const float*)d_in[3];
    const float* Wv = (const float*)d_in[4];
    const float* Wo = (const float*)d_in[5];
    float* out = (float*)d_out;

    cudaFuncSetAttribute(flash_mma_kernel,
                         cudaFuncAttributeMaxDynamicSharedMemorySize, FLASH_SMEM);
    cudaFuncSetAttribute(gemm_mma_kernel<0>,
                         cudaFuncAttributeMaxDynamicSharedMemorySize, GEMM_SMEM);
    cudaFuncSetAttribute(gemm_mma_kernel<1>,
                         cudaFuncAttributeMaxDynamicSharedMemorySize, GEMM_SMEM);

    rope_table_kernel<<<(TT * 32 + 255) / 256, 256>>>();

    gemm_mma_kernel<0><<<dim3(MROWS / 256, 3072 / 128), 256, GEMM_SMEM>>>(
        x, Wq, Wk, Wv, nullptr);

    flash_mma_kernel<<<dim3(TT / 128, NH, BB), 256, FLASH_SMEM>>>();

    gemm_mma_kernel<1><<<dim3(MROWS / 256, DMODEL / 128), 256, GEMM_SMEM>>>(
        nullptr, Wo, nullptr, nullptr, out);
}